// round 1
// baseline (speedup 1.0000x reference)
#include <cuda_runtime.h>

#define BB   32
#define LL   2048
#define DIN  64
#define NC   32
#define DC   16
#define NOUT 512        // NC*DC
#define NCH  16         // chunks for heavy iter kernel
#define LCH  (LL/NCH)   // 128 rows per CTA
#define NCH0 64         // chunks for iteration-0 reduction
#define ROWS0 (LL/NCH0) // 32 rows per CTA

// Scratch (no allocations allowed) ------------------------------------------
__device__ float g_part0[BB * NCH0 * DIN];      // iter-0 partial sums (512 KB)
__device__ float g_part [BB * NCH  * NC * DIN]; // per-chunk s partials (4 MB)
__device__ float g_v    [BB * NC * DIN];        // v[b,n,i] = W_n . outputs[b,n,:]

// Packed f32x2 helpers -------------------------------------------------------
__device__ __forceinline__ void ffma2(unsigned long long& d,
                                      unsigned long long a,
                                      unsigned long long b) {
    asm volatile("fma.rn.f32x2 %0, %1, %2, %0;" : "+l"(d) : "l"(a), "l"(b));
}
__device__ __forceinline__ void addf2(unsigned long long& d, unsigned long long a) {
    asm volatile("add.rn.f32x2 %0, %0, %1;" : "+l"(d) : "l"(a));
}
__device__ __forceinline__ void lds_v2b64(unsigned long long& a,
                                          unsigned long long& b,
                                          unsigned addr) {
    asm volatile("ld.shared.v2.b64 {%0, %1}, [%2];" : "=l"(a), "=l"(b) : "r"(addr));
}
__device__ __forceinline__ unsigned long long pack2(float x, float y) {
    unsigned long long r;
    asm("mov.b64 %0, {%1, %2};" : "=l"(r) : "f"(x), "f"(y));
    return r;
}
__device__ __forceinline__ float2 unpack2(unsigned long long v) {
    float2 r;
    asm("mov.b64 {%0, %1}, %2;" : "=f"(r.x), "=f"(r.y) : "l"(v));
    return r;
}

// ----------------------------------------------------------------------------
// Kernel 1: iteration-0 reduction. c = softmax(0) is uniform, so
// s is (up to scale, and squash is scale-invariant) just sum_l u[b,l,i].
// grid (NCH0, B), block 256.
// ----------------------------------------------------------------------------
__global__ __launch_bounds__(256) void reduce0_kernel(const float* __restrict__ u) {
    int b = blockIdx.y, ch = blockIdx.x;
    int t = threadIdx.x;
    int g = t >> 6, i = t & 63;
    const float* up = u + ((size_t)b * LL + (size_t)ch * ROWS0 + g) * DIN + i;
    float acc = 0.f;
#pragma unroll
    for (int j = 0; j < ROWS0 / 4; j++) acc += up[(size_t)j * 4 * DIN];
    __shared__ float red[4][64];
    red[g][i] = acc;
    __syncthreads();
    if (t < 64) {
        float s = red[0][t] + red[1][t] + red[2][t] + red[3][t];
        g_part0[((size_t)b * NCH0 + ch) * DIN + t] = s;
    }
}

// ----------------------------------------------------------------------------
// Kernel 2: finalize. Reduce s partials, project through W per capsule,
// squash (pure L2 normalize, eps=1e-7), optionally write output and/or
// compute v[b,n,i] = sum_d outputs[b,n,d] * W[i, n*16+d].
// grid B, block 512 (thread t == output slot n*16+d).
// ----------------------------------------------------------------------------
__global__ __launch_bounds__(512) void finalize_kernel(int per_n,
                                                       const float* __restrict__ W,
                                                       float* __restrict__ out,
                                                       int want_v) {
    int b = blockIdx.x, t = threadIdx.x;
    __shared__ float s_sh[NC * DIN];  // s[b, n, i]
    __shared__ float o_sh[NC * DC];   // outputs[b, n, d]

    if (per_n) {
        for (int e = t; e < NC * DIN; e += 512) {
            float acc = 0.f;
            for (int ch = 0; ch < NCH; ch++)
                acc += g_part[((size_t)b * NCH + ch) * (NC * DIN) + e];
            s_sh[e] = acc;
        }
    } else {
        if (t < DIN) {
            float acc = 0.f;
            for (int ch = 0; ch < NCH0; ch++)
                acc += g_part0[((size_t)b * NCH0 + ch) * DIN + t];
#pragma unroll
            for (int n = 0; n < NC; n++) s_sh[n * DIN + t] = acc;
        }
    }
    __syncthreads();

    int n = t >> 4;
    float acc = 0.f;
#pragma unroll 8
    for (int i = 0; i < DIN; i++) acc += s_sh[n * DIN + i] * W[i * NOUT + t];

    // squash: x / sqrt(sum_d x^2 + 1e-7), reduce within 16-lane group
    float s2 = acc * acc;
#pragma unroll
    for (int off = 8; off; off >>= 1)
        s2 += __shfl_xor_sync(0xffffffffu, s2, off, 16);
    float o = acc * rsqrtf(s2 + 1e-7f);
    o_sh[t] = o;
    if (out) out[(size_t)b * NOUT + t] = o;
    __syncthreads();

    if (want_v) {
        for (int e = t; e < NC * DIN; e += 512) {
            int nn = e >> 6, ii = e & 63;
            float a = 0.f;
#pragma unroll
            for (int d = 0; d < DC; d++)
                a += o_sh[nn * DC + d] * W[ii * NOUT + nn * DC + d];
            g_v[(size_t)b * (NC * DIN) + e] = a;
        }
    }
}

// ----------------------------------------------------------------------------
// Kernel 3: fused routing iteration.
// For each l: logits[n] = u[l,:].v[n,:]  ->  softmax over n  ->
//             s[n,:] += c[n] * u[l,:]
// Per warp: lane == capsule n. v and s live entirely in registers (packed
// f32x2). u rows are staged in SMEM and broadcast-read as 16B chunks.
// grid (NCH, B), block 128 (4 warps, each owns 1/4 of the chunk rows).
// ----------------------------------------------------------------------------
__global__ __launch_bounds__(128) void iter_kernel(const float* __restrict__ u) {
    int b = blockIdx.y, ch = blockIdx.x;
    int t = threadIdx.x, w = t >> 5, lane = t & 31;

    __shared__ float4 ush4[32 * 16];        // 32-row tile of u  (8 KB)
    __shared__ float  red[4 * NC * 65];     // warp partials, padded (33.3 KB)

    unsigned long long vreg[32], sreg[32];
    const unsigned long long* vp =
        (const unsigned long long*)(g_v + ((size_t)b * NC + lane) * DIN);
#pragma unroll
    for (int k = 0; k < 32; k++) vreg[k] = vp[k];
#pragma unroll
    for (int k = 0; k < 32; k++) sreg[k] = 0ULL;

    unsigned ush_addr = (unsigned)__cvta_generic_to_shared(ush4);
    const float4* ug = (const float4*)u;

    for (int tile = 0; tile < LCH / 32; tile++) {
        size_t gbase = ((size_t)b * LL + (size_t)ch * LCH + tile * 32) * 16;
#pragma unroll
        for (int j = 0; j < 4; j++) ush4[t + 128 * j] = ug[gbase + t + 128 * j];
        __syncthreads();

#pragma unroll 2
        for (int r = 0; r < 8; r++) {
            unsigned addr = ush_addr + (unsigned)((w * 8 + r) * 256);
            // logits: 4 independent accumulator chains
            unsigned long long a0 = 0ULL, a1 = 0ULL, a2 = 0ULL, a3 = 0ULL;
#pragma unroll
            for (int k = 0; k < 8; k++) {
                unsigned long long ua, ub, uc, ud;
                lds_v2b64(ua, ub, addr + k * 32);
                lds_v2b64(uc, ud, addr + k * 32 + 16);
                ffma2(a0, ua, vreg[4 * k + 0]);
                ffma2(a1, ub, vreg[4 * k + 1]);
                ffma2(a2, uc, vreg[4 * k + 2]);
                ffma2(a3, ud, vreg[4 * k + 3]);
            }
            addf2(a0, a1);
            addf2(a2, a3);
            addf2(a0, a2);
            float2 lh = unpack2(a0);
            float logit = lh.x + lh.y;

            // softmax over 32 lanes (logits are small: no max-subtract needed)
            float e = __expf(logit);
            float ssum = e;
#pragma unroll
            for (int off = 16; off; off >>= 1)
                ssum += __shfl_xor_sync(0xffffffffu, ssum, off);
            float c = __fdividef(e, ssum);
            unsigned long long c2 = pack2(c, c);

            // s[n,:] += c * u[l,:]
#pragma unroll
            for (int k = 0; k < 16; k++) {
                unsigned long long ua, ub;
                lds_v2b64(ua, ub, addr + k * 16);
                ffma2(sreg[2 * k + 0], c2, ua);
                ffma2(sreg[2 * k + 1], c2, ub);
            }
        }
        __syncthreads();
    }

    // Cross-warp reduction of s partials
    float* myred = red + ((size_t)w * NC + lane) * 65;
#pragma unroll
    for (int k = 0; k < 32; k++) {
        float2 v2 = unpack2(sreg[k]);
        myred[2 * k] = v2.x;
        myred[2 * k + 1] = v2.y;
    }
    __syncthreads();
    float* gp = g_part + ((size_t)b * NCH + ch) * (NC * DIN);
    for (int e = t; e < NC * DIN; e += 128) {
        int n = e >> 6, i = e & 63;
        float a = red[(0 * NC + n) * 65 + i] + red[(1 * NC + n) * 65 + i] +
                  red[(2 * NC + n) * 65 + i] + red[(3 * NC + n) * 65 + i];
        gp[e] = a;
    }
}

// ----------------------------------------------------------------------------
extern "C" void kernel_launch(void* const* d_in, const int* in_sizes, int n_in,
                              void* d_out, int out_size) {
    (void)n_in; (void)out_size;
    const float* u = (const float*)d_in[0];
    const float* W = (const float*)d_in[1];
    if (in_sizes[0] < in_sizes[1]) {  // defensive: u is the big tensor
        const float* tmp = u; u = W; W = tmp;
    }
    float* out = (float*)d_out;

    dim3 g0(NCH0, BB), gi(NCH, BB);

    // iteration 0: uniform c -> plain sum over l
    reduce0_kernel<<<g0, 256>>>(u);
    finalize_kernel<<<BB, 512>>>(/*per_n=*/0, W, /*out=*/nullptr, /*want_v=*/1);
    // iteration 1
    iter_kernel<<<gi, 128>>>(u);
    finalize_kernel<<<BB, 512>>>(/*per_n=*/1, W, /*out=*/nullptr, /*want_v=*/1);
    // iteration 2 (final)
    iter_kernel<<<gi, 128>>>(u);
    finalize_kernel<<<BB, 512>>>(/*per_n=*/1, W, /*out=*/out, /*want_v=*/0);
}

// round 2
// speedup vs baseline: 2.0319x; 2.0319x over previous
#include <cuda_runtime.h>

#define BB   32
#define LL   2048
#define DIN  64
#define NC   32
#define DC   16
#define NOUT 512        // NC*DC
#define NCH  32         // chunks for heavy iter kernel
#define LCH  (LL/NCH)   // 64 rows per CTA
#define NCH0 32         // chunks for iteration-0 reduction
#define ROWS0 (LL/NCH0) // 64 rows per CTA

// Scratch (no allocations allowed) ------------------------------------------
__device__ float g_part0[BB * NCH0 * DIN];      // iter-0 partial sums (256 KB)
__device__ float g_part [BB * NCH  * NC * DIN]; // per-chunk s partials (8 MB)
__device__ float g_v    [BB * NC * DIN];        // v[b,n,i] = W_n . outputs[b,n,:]

// Packed f32x2 helpers -------------------------------------------------------
__device__ __forceinline__ void ffma2(unsigned long long& d,
                                      unsigned long long a,
                                      unsigned long long b) {
    asm volatile("fma.rn.f32x2 %0, %1, %2, %0;" : "+l"(d) : "l"(a), "l"(b));
}
__device__ __forceinline__ void addf2(unsigned long long& d, unsigned long long a) {
    asm volatile("add.rn.f32x2 %0, %0, %1;" : "+l"(d) : "l"(a));
}
__device__ __forceinline__ void lds_v2b64(unsigned long long& a,
                                          unsigned long long& b,
                                          unsigned addr) {
    asm volatile("ld.shared.v2.b64 {%0, %1}, [%2];" : "=l"(a), "=l"(b) : "r"(addr));
}
__device__ __forceinline__ unsigned long long pack2(float x, float y) {
    unsigned long long r;
    asm("mov.b64 %0, {%1, %2};" : "=l"(r) : "f"(x), "f"(y));
    return r;
}
__device__ __forceinline__ float2 unpack2(unsigned long long v) {
    float2 r;
    asm("mov.b64 {%0, %1}, %2;" : "=f"(r.x), "=f"(r.y) : "l"(v));
    return r;
}

// ----------------------------------------------------------------------------
// Kernel 1: iteration-0 reduction. c = softmax(0) is uniform, so
// s is (up to scale; squash is scale-invariant) just sum_l u[b,l,i].
// grid (NCH0, B), block 256.
// ----------------------------------------------------------------------------
__global__ __launch_bounds__(256) void reduce0_kernel(const float* __restrict__ u) {
    int b = blockIdx.y, ch = blockIdx.x;
    int t = threadIdx.x;
    int g = t >> 6, i = t & 63;
    const float* up = u + ((size_t)b * LL + (size_t)ch * ROWS0 + g) * DIN + i;
    float acc = 0.f;
#pragma unroll
    for (int j = 0; j < ROWS0 / 4; j++) acc += up[(size_t)j * 4 * DIN];
    __shared__ float red[4][64];
    red[g][i] = acc;
    __syncthreads();
    if (t < 64) {
        float s = red[0][t] + red[1][t] + red[2][t] + red[3][t];
        g_part0[((size_t)b * NCH0 + ch) * DIN + t] = s;
    }
}

// ----------------------------------------------------------------------------
// Kernel 2: finalize, one WARP per (b, n) capsule.
// grid (NC/4, B), block 128 (warp w -> capsule n = blockIdx.x*4 + w).
// Steps: reduce s partials (coalesced, unrolled) -> project through W_n ->
// squash (16-lane shuffle) -> write out and/or v[b,n,:].
// ----------------------------------------------------------------------------
__global__ __launch_bounds__(128) void finalize_kernel(int per_n,
                                                       const float* __restrict__ W,
                                                       float* __restrict__ out,
                                                       int want_v) {
    int b = blockIdx.y;
    int w = threadIdx.x >> 5, lane = threadIdx.x & 31;
    int n = blockIdx.x * 4 + w;

    // 1. reduce s over chunks: lane holds s[lane], s[lane+32]
    float s0 = 0.f, s1 = 0.f;
    if (per_n) {
        const float* gp = g_part + (((size_t)b * NCH) * NC + n) * DIN;
#pragma unroll
        for (int ch = 0; ch < NCH; ch++) {
            s0 += gp[(size_t)ch * (NC * DIN) + lane];
            s1 += gp[(size_t)ch * (NC * DIN) + lane + 32];
        }
    } else {
        const float* gp = g_part0 + (size_t)b * NCH0 * DIN;
#pragma unroll
        for (int ch = 0; ch < NCH0; ch++) {
            s0 += gp[ch * DIN + lane];
            s1 += gp[ch * DIN + lane + 32];
        }
    }

    __shared__ float s_sh[4][DIN];
    s_sh[w][lane] = s0;
    s_sh[w][lane + 32] = s1;
    __syncwarp();

    // 2. projection: o[d] = sum_i s[i] * W[i*512 + n*16 + d]
    // lane = d + 16*half; each half sums 32 i's, then combine across halves.
    int d = lane & 15, half = lane >> 4;
    float acc = 0.f;
    {
        const float* Wp = W + (size_t)(half * 32) * NOUT + n * DC + d;
#pragma unroll
        for (int i = 0; i < 32; i++)
            acc += s_sh[w][half * 32 + i] * Wp[(size_t)i * NOUT];
    }
    acc += __shfl_xor_sync(0xffffffffu, acc, 16);
    // now lanes d and d+16 both hold o[d] (pre-squash)

    // 3. squash: o / sqrt(sum_d o^2 + 1e-7), reduce within 16-lane group
    float s2 = acc * acc;
#pragma unroll
    for (int off = 8; off; off >>= 1)
        s2 += __shfl_xor_sync(0xffffffffu, s2, off, 16);
    float o = acc * rsqrtf(s2 + 1e-7f);

    if (out && lane < 16) out[(size_t)b * NOUT + n * DC + lane] = o;

    // 4. v[i] = sum_d o[d] * W[i*512 + n*16 + d], lane handles i=lane, lane+32
    if (want_v) {
        const float4* w0 = (const float4*)(W + (size_t)lane * NOUT + n * DC);
        const float4* w1 = (const float4*)(W + (size_t)(lane + 32) * NOUT + n * DC);
        float v0 = 0.f, v1 = 0.f;
#pragma unroll
        for (int q = 0; q < 4; q++) {
            float4 a = w0[(size_t)q];
            float4 c = w1[(size_t)q];
            float o0 = __shfl_sync(0xffffffffu, o, 4 * q + 0);
            float o1 = __shfl_sync(0xffffffffu, o, 4 * q + 1);
            float o2 = __shfl_sync(0xffffffffu, o, 4 * q + 2);
            float o3 = __shfl_sync(0xffffffffu, o, 4 * q + 3);
            v0 += a.x * o0 + a.y * o1 + a.z * o2 + a.w * o3;
            v1 += c.x * o0 + c.y * o1 + c.z * o2 + c.w * o3;
        }
        float* vp = g_v + ((size_t)b * NC + n) * DIN;
        vp[lane] = v0;
        vp[lane + 32] = v1;
    }
}

// ----------------------------------------------------------------------------
// Kernel 3: fused routing iteration.
// For each l: logits[n] = u[l,:].v[n,:]  ->  softmax over n  ->
//             s[n,:] += c[n] * u[l,:]
// Per warp: lane == capsule n. v and s live entirely in registers (packed
// f32x2). u rows staged in SMEM, broadcast-read as 16B chunks.
// Softmax is batched 4 rows at a time so the 4 shuffle-reduce chains
// overlap (SHFL latency ~26 cyc is the per-row critical path otherwise).
// grid (NCH, B), block 128 (4 warps, each owns 1/4 of the chunk rows).
// ----------------------------------------------------------------------------
__global__ __launch_bounds__(128) void iter_kernel(const float* __restrict__ u) {
    int b = blockIdx.y, ch = blockIdx.x;
    int t = threadIdx.x, w = t >> 5, lane = t & 31;

    __shared__ float4 ush4[32 * 16];        // 32-row tile of u  (8 KB)
    __shared__ float  red[4 * NC * 65];     // warp partials, padded (33.3 KB)

    unsigned long long vreg[32], sreg[32];
    const unsigned long long* vp =
        (const unsigned long long*)(g_v + ((size_t)b * NC + lane) * DIN);
#pragma unroll
    for (int k = 0; k < 32; k++) vreg[k] = vp[k];
#pragma unroll
    for (int k = 0; k < 32; k++) sreg[k] = 0ULL;

    unsigned ush_addr = (unsigned)__cvta_generic_to_shared(ush4);
    const float4* ug = (const float4*)u;

    for (int tile = 0; tile < LCH / 32; tile++) {
        size_t gbase = ((size_t)b * LL + (size_t)ch * LCH + tile * 32) * 16;
#pragma unroll
        for (int j = 0; j < 4; j++) ush4[t + 128 * j] = ug[gbase + t + 128 * j];
        __syncthreads();

        for (int rb = 0; rb < 2; rb++) {   // 2 batches of 4 rows per warp
            float lg[4];
            // --- phase 1: logits for 4 rows ---
#pragma unroll
            for (int rr = 0; rr < 4; rr++) {
                unsigned addr = ush_addr + (unsigned)((w * 8 + rb * 4 + rr) * 256);
                unsigned long long a0 = 0ULL, a1 = 0ULL, a2 = 0ULL, a3 = 0ULL;
#pragma unroll
                for (int k = 0; k < 8; k++) {
                    unsigned long long ua, ub, uc, ud;
                    lds_v2b64(ua, ub, addr + k * 32);
                    lds_v2b64(uc, ud, addr + k * 32 + 16);
                    ffma2(a0, ua, vreg[4 * k + 0]);
                    ffma2(a1, ub, vreg[4 * k + 1]);
                    ffma2(a2, uc, vreg[4 * k + 2]);
                    ffma2(a3, ud, vreg[4 * k + 3]);
                }
                addf2(a0, a1);
                addf2(a2, a3);
                addf2(a0, a2);
                float2 lh = unpack2(a0);
                lg[rr] = lh.x + lh.y;
            }
            // --- phase 2: 4 interleaved softmaxes over the 32 lanes ---
            float ex[4], ss[4];
#pragma unroll
            for (int rr = 0; rr < 4; rr++) { ex[rr] = __expf(lg[rr]); ss[rr] = ex[rr]; }
#pragma unroll
            for (int off = 16; off; off >>= 1) {
#pragma unroll
                for (int rr = 0; rr < 4; rr++)
                    ss[rr] += __shfl_xor_sync(0xffffffffu, ss[rr], off);
            }
            unsigned long long c2[4];
#pragma unroll
            for (int rr = 0; rr < 4; rr++) {
                float c = __fdividef(ex[rr], ss[rr]);
                c2[rr] = pack2(c, c);
            }
            // --- phase 3: s[n,:] += c * u[l,:] for the 4 rows ---
#pragma unroll
            for (int rr = 0; rr < 4; rr++) {
                unsigned addr = ush_addr + (unsigned)((w * 8 + rb * 4 + rr) * 256);
#pragma unroll
                for (int k = 0; k < 16; k++) {
                    unsigned long long ua, ub;
                    lds_v2b64(ua, ub, addr + k * 16);
                    ffma2(sreg[2 * k + 0], c2[rr], ua);
                    ffma2(sreg[2 * k + 1], c2[rr], ub);
                }
            }
        }
        __syncthreads();
    }

    // Cross-warp reduction of s partials, coalesced write to g_part
    float* myred = red + ((size_t)w * NC + lane) * 65;
#pragma unroll
    for (int k = 0; k < 32; k++) {
        float2 v2 = unpack2(sreg[k]);
        myred[2 * k] = v2.x;
        myred[2 * k + 1] = v2.y;
    }
    __syncthreads();
    float* gp = g_part + ((size_t)b * NCH + ch) * (NC * DIN);
    for (int e = t; e < NC * DIN; e += 128) {
        int n = e >> 6, i = e & 63;
        float a = red[(0 * NC + n) * 65 + i] + red[(1 * NC + n) * 65 + i] +
                  red[(2 * NC + n) * 65 + i] + red[(3 * NC + n) * 65 + i];
        gp[e] = a;
    }
}

// ----------------------------------------------------------------------------
extern "C" void kernel_launch(void* const* d_in, const int* in_sizes, int n_in,
                              void* d_out, int out_size) {
    (void)n_in; (void)out_size;
    const float* u = (const float*)d_in[0];
    const float* W = (const float*)d_in[1];
    if (in_sizes[0] < in_sizes[1]) {  // defensive: u is the big tensor
        const float* tmp = u; u = W; W = tmp;
    }
    float* out = (float*)d_out;

    dim3 g0(NCH0, BB), gi(NCH, BB), gf(NC / 4, BB);

    // iteration 0: uniform c -> plain sum over l
    reduce0_kernel<<<g0, 256>>>(u);
    finalize_kernel<<<gf, 128>>>(/*per_n=*/0, W, /*out=*/nullptr, /*want_v=*/1);
    // iteration 1
    iter_kernel<<<gi, 128>>>(u);
    finalize_kernel<<<gf, 128>>>(/*per_n=*/1, W, /*out=*/nullptr, /*want_v=*/1);
    // iteration 2 (final)
    iter_kernel<<<gi, 128>>>(u);
    finalize_kernel<<<gf, 128>>>(/*per_n=*/1, W, /*out=*/out, /*want_v=*/0);
}